// round 5
// baseline (speedup 1.0000x reference)
#include <cuda_runtime.h>
#include <cstdint>

#define B_    32
#define C_    320
#define H_    64
#define W_    64
#define CTXD  1024
#define KIN   1026     // 1024 context channels + 2 indicator channels
#define KPAD  1056     // padded to 32-multiple for the transpose tiling
#define CHW   16
#define P_    256      // 16*16 spatial positions
#define PADP  324      // 18*18 zero-padded spatial
#define CICH  12       // input-channel chunk staged in SMEM

// ---- scratch (device globals: allocation-free by construction) ----
__device__ float g_ctxT[(size_t)B_ * KPAD * P_];   // transposed ctx (B, ci, p)   ~34.6MB
__device__ float g_cx1 [(size_t)B_ * C_ * PADP];   // conv1+SiLU, padded 18x18    ~13.3MB (borders stay 0)
__device__ float g_cx2 [(size_t)B_ * C_ * P_];     // conv2 out                   ~10.5MB
__device__ int   g_bbi [B_ * 8];                   // x1,y1,x2,y2,ok,dx,dy

// ---- packed fp32x2 helpers (FFMA2: 2x fp32 FMA per issue, exact fp32) ----
__device__ __forceinline__ unsigned long long ffma2(unsigned long long a,
                                                    unsigned long long b,
                                                    unsigned long long c) {
    unsigned long long d;
    asm("fma.rn.f32x2 %0, %1, %2, %3;" : "=l"(d) : "l"(a), "l"(b), "l"(c));
    return d;
}
__device__ __forceinline__ unsigned long long dup2(float x) {
    unsigned long long d;
    asm("mov.b64 %0, {%1, %1};" : "=l"(d) : "f"(x), "f"(x));
    return d;
}

// ---------------------------------------------------------------------------
// bbox -> int precompute (matches jnp: (bbox*64) truncated to int32)
// ---------------------------------------------------------------------------
__global__ void bbox_prep_kernel(const float* __restrict__ bbox) {
    int b = threadIdx.x;
    if (b >= B_) return;
    int x1 = (int)(bbox[4 * b + 0] * 64.0f);
    int y1 = (int)(bbox[4 * b + 1] * 64.0f);
    int x2 = (int)(bbox[4 * b + 2] * 64.0f);
    int y2 = (int)(bbox[4 * b + 3] * 64.0f);
    x2 = max(x2, x1 + 1);
    y2 = max(y2, y1 + 1);
    int ok = (y2 <= H_) && (x2 <= W_) && (y1 >= 0) && (x1 >= 0);
    int* o = &g_bbi[b * 8];
    o[0] = x1; o[1] = y1; o[2] = x2; o[3] = y2;
    o[4] = ok; o[5] = x2 - x1; o[6] = y2 - y1;
}

// ---------------------------------------------------------------------------
// context (B,256,1024) + indicator -> g_ctxT (B, 1056, 256), coalesced both ways
// rows 1024/1025 = indicator, rows >=1026 = 0
// ---------------------------------------------------------------------------
__global__ void transpose_kernel(const float* __restrict__ context,
                                 const float* __restrict__ indicator) {
    __shared__ float tile[32][33];
    int b   = blockIdx.z;
    int ci0 = blockIdx.y * 32;
    int p0  = blockIdx.x * 32;
    int tx = threadIdx.x, ty = threadIdx.y;
#pragma unroll
    for (int j = 0; j < 4; ++j) {
        int p  = p0 + ty + 8 * j;
        int ci = ci0 + tx;
        float v;
        if (ci < CTXD)      v = context[((size_t)b * P_ + p) * CTXD + ci];
        else if (ci < KIN)  v = indicator[b * 2 + (ci - CTXD)];
        else                v = 0.0f;
        tile[ty + 8 * j][tx] = v;
    }
    __syncthreads();
#pragma unroll
    for (int j = 0; j < 4; ++j) {
        int ci = ci0 + ty + 8 * j;
        int p  = p0 + tx;
        g_ctxT[((size_t)b * KPAD + ci) * P_ + p] = tile[tx][ty + 8 * j];
    }
}

// ---------------------------------------------------------------------------
// conv1 (K=1026 via 86 chunks of 12) + SiLU -> padded g_cx1
// CTA tile: 16 out-channels x 256 positions. thread = 2 positions x 4 co-pairs.
// ---------------------------------------------------------------------------
__global__ __launch_bounds__(256) void conv1_kernel(const float* __restrict__ w_in,
                                                    const float* __restrict__ b_in) {
    __shared__ __align__(16) float sX[CICH][PADP];
    __shared__ __align__(16) float sW[CICH][9][16];
    int t   = threadIdx.x;
    int co0 = blockIdx.x * 16;
    int b   = blockIdx.y;

    // zero the padded borders once; interiors are rewritten every chunk
    for (int idx = t; idx < CICH * PADP; idx += 256) {
        int q  = idx % PADP;
        int qy = q / 18, qx = q % 18;
        if (qy == 0 || qy == 17 || qx == 0 || qx == 17) (&sX[0][0])[idx] = 0.0f;
    }

    int co_half = t >> 7;                 // 0..1 : co sub-range [0,8) or [8,16)
    int pi = t & 127;
    int p0 = pi * 2;                      // even position
    int y = p0 >> 4, x = p0 & 15;
    int cbase = (y + 1) * 18 + (x + 1);   // center index in padded 18x18

    unsigned long long acc[2][4];
#pragma unroll
    for (int i = 0; i < 2; ++i)
#pragma unroll
        for (int j = 0; j < 4; ++j) acc[i][j] = 0ull;

    const int NCH = (KIN + CICH - 1) / CICH;   // 86
    for (int ch = 0; ch < NCH; ++ch) {
        int ci0 = ch * CICH;
        __syncthreads();
        // stage X interior (coalesced from transposed layout)
        for (int idx = t; idx < CICH * P_; idx += 256) {
            int ci = idx >> 8;
            int p  = idx & 255;
            int py = p >> 4, px = p & 15;
            sX[ci][(py + 1) * 18 + px + 1] =
                g_ctxT[((size_t)b * KPAD + ci0 + ci) * P_ + p];
        }
        // stage W (zero past K=1026)
        for (int idx = t; idx < CICH * 9 * 16; idx += 256) {
            int co = idx & 15;
            int k  = idx >> 4;
            int ci = k / 9, tap = k - ci * 9;
            int gci = ci0 + ci;
            sW[ci][tap][co] = (gci < KIN)
                ? w_in[((size_t)(co0 + co) * KIN + gci) * 9 + tap] : 0.0f;
        }
        __syncthreads();
#pragma unroll 1
        for (int ci = 0; ci < CICH; ++ci) {
#pragma unroll
            for (int tap = 0; tap < 9; ++tap) {
                int off = (tap / 3) * 18 + (tap % 3) - 19;   // (dy-1)*18 + (dx-1)
                float xv0 = sX[ci][cbase + off];
                float xv1 = sX[ci][cbase + off + 1];
                unsigned long long xd0 = dup2(xv0), xd1 = dup2(xv1);
                const unsigned long long* wrow =
                    reinterpret_cast<const unsigned long long*>(&sW[ci][tap][co_half * 8]);
#pragma unroll
                for (int cp = 0; cp < 4; ++cp) {
                    unsigned long long w2 = wrow[cp];
                    acc[0][cp] = ffma2(w2, xd0, acc[0][cp]);
                    acc[1][cp] = ffma2(w2, xd1, acc[1][cp]);
                }
            }
        }
    }
    // epilogue: bias + SiLU, write padded interior
#pragma unroll
    for (int pos = 0; pos < 2; ++pos)
#pragma unroll
        for (int cp = 0; cp < 4; ++cp) {
            int coL = co0 + co_half * 8 + 2 * cp;
            unsigned long long a = acc[pos][cp];
            float v0 = __uint_as_float((unsigned)(a & 0xffffffffull)) + b_in[coL];
            float v1 = __uint_as_float((unsigned)(a >> 32)) + b_in[coL + 1];
            float s0 = v0 / (1.0f + expf(-v0));
            float s1 = v1 / (1.0f + expf(-v1));
            size_t base = ((size_t)b * C_ + coL) * PADP + cbase + pos;
            g_cx1[base]        = s0;
            g_cx1[base + PADP] = s1;
        }
}

// ---------------------------------------------------------------------------
// conv2 (K=320 via 27 chunks of 12) -> g_cx2 (no activation)
// input g_cx1 is already zero-padded, so staging is a straight copy
// ---------------------------------------------------------------------------
__global__ __launch_bounds__(256) void conv2_kernel(const float* __restrict__ w_out,
                                                    const float* __restrict__ b_out) {
    __shared__ __align__(16) float sX[CICH][PADP];
    __shared__ __align__(16) float sW[CICH][9][16];
    int t   = threadIdx.x;
    int co0 = blockIdx.x * 16;
    int b   = blockIdx.y;

    int co_half = t >> 7;
    int pi = t & 127;
    int p0 = pi * 2;
    int y = p0 >> 4, x = p0 & 15;
    int cbase = (y + 1) * 18 + (x + 1);

    unsigned long long acc[2][4];
#pragma unroll
    for (int i = 0; i < 2; ++i)
#pragma unroll
        for (int j = 0; j < 4; ++j) acc[i][j] = 0ull;

    const int NCH = (C_ + CICH - 1) / CICH;    // 27
    for (int ch = 0; ch < NCH; ++ch) {
        int ci0 = ch * CICH;
        __syncthreads();
        for (int idx = t; idx < CICH * PADP; idx += 256) {
            int ci = idx / PADP;
            int q  = idx - ci * PADP;
            int gci = ci0 + ci;
            sX[ci][q] = (gci < C_) ? g_cx1[((size_t)b * C_ + gci) * PADP + q] : 0.0f;
        }
        for (int idx = t; idx < CICH * 9 * 16; idx += 256) {
            int co = idx & 15;
            int k  = idx >> 4;
            int ci = k / 9, tap = k - ci * 9;
            int gci = ci0 + ci;
            sW[ci][tap][co] = (gci < C_)
                ? w_out[((size_t)(co0 + co) * C_ + gci) * 9 + tap] : 0.0f;
        }
        __syncthreads();
#pragma unroll 1
        for (int ci = 0; ci < CICH; ++ci) {
#pragma unroll
            for (int tap = 0; tap < 9; ++tap) {
                int off = (tap / 3) * 18 + (tap % 3) - 19;
                float xv0 = sX[ci][cbase + off];
                float xv1 = sX[ci][cbase + off + 1];
                unsigned long long xd0 = dup2(xv0), xd1 = dup2(xv1);
                const unsigned long long* wrow =
                    reinterpret_cast<const unsigned long long*>(&sW[ci][tap][co_half * 8]);
#pragma unroll
                for (int cp = 0; cp < 4; ++cp) {
                    unsigned long long w2 = wrow[cp];
                    acc[0][cp] = ffma2(w2, xd0, acc[0][cp]);
                    acc[1][cp] = ffma2(w2, xd1, acc[1][cp]);
                }
            }
        }
    }
#pragma unroll
    for (int pos = 0; pos < 2; ++pos)
#pragma unroll
        for (int cp = 0; cp < 4; ++cp) {
            int coL = co0 + co_half * 8 + 2 * cp;
            unsigned long long a = acc[pos][cp];
            float v0 = __uint_as_float((unsigned)(a & 0xffffffffull)) + b_out[coL];
            float v1 = __uint_as_float((unsigned)(a >> 32)) + b_out[coL + 1];
            size_t base = ((size_t)b * C_ + coL) * P_ + p0 + pos;
            g_cx2[base]      = v0;
            g_cx2[base + P_] = v1;
        }
}

// ---------------------------------------------------------------------------
// out = global_x + masked nearest-neighbor upsample of g_cx2 into the bbox
// ---------------------------------------------------------------------------
__global__ __launch_bounds__(256) void fuse_kernel(const float* __restrict__ gx,
                                                   float* __restrict__ out) {
    int idx = blockIdx.x * 256 + threadIdx.x;    // (bc*64 + y)*16 + xg
    int xg = idx & 15;
    int y  = (idx >> 4) & 63;
    int bc = idx >> 10;                           // b*C_ + c
    int b  = bc / C_;

    size_t gbase = (((size_t)bc * 64 + y) * 64) + xg * 4;
    float4 g = *reinterpret_cast<const float4*>(gx + gbase);

    const int* bb = &g_bbi[b * 8];
    int x1 = bb[0], y1 = bb[1], x2 = bb[2], y2 = bb[3];
    int ok = bb[4], dxs = bb[5], dys = bb[6];

    if (ok && y >= y1 && y < y2) {
        int sy = (y - y1) * CHW / dys;
        sy = min(max(sy, 0), CHW - 1);
        const float* lrow = g_cx2 + (size_t)bc * P_ + sy * CHW;
        int xb = xg * 4;
        float* gv = reinterpret_cast<float*>(&g);
#pragma unroll
        for (int k = 0; k < 4; ++k) {
            int xx = xb + k;
            if (xx >= x1 && xx < x2) {
                int sx = (xx - x1) * CHW / dxs;
                sx = min(max(sx, 0), CHW - 1);
                gv[k] += lrow[sx];
            }
        }
    }
    *reinterpret_cast<float4*>(out + gbase) = g;
}

// ---------------------------------------------------------------------------
extern "C" void kernel_launch(void* const* d_in, const int* in_sizes, int n_in,
                              void* d_out, int out_size) {
    const float* global_x  = (const float*)d_in[0];
    const float* context   = (const float*)d_in[1];
    const float* indicator = (const float*)d_in[2];
    const float* bbox      = (const float*)d_in[3];
    const float* w_in      = (const float*)d_in[4];
    const float* b_in      = (const float*)d_in[5];
    const float* w_out     = (const float*)d_in[6];
    const float* b_out     = (const float*)d_in[7];
    float* out = (float*)d_out;

    bbox_prep_kernel<<<1, 32>>>(bbox);
    transpose_kernel<<<dim3(8, 33, 32), dim3(32, 8)>>>(context, indicator);
    conv1_kernel<<<dim3(20, 32), 256>>>(w_in, b_in);
    conv2_kernel<<<dim3(20, 32), 256>>>(w_out, b_out);
    fuse_kernel<<<(B_ * C_ * H_ * (W_ / 4)) / 256, 256>>>(global_x, out);
}